// round 3
// baseline (speedup 1.0000x reference)
#include <cuda_runtime.h>
#include <cstdint>

// NNUE HalfKP forward — all integer inputs arrive widened to int32 by the harness.
//   kernel 0: zero scalar accumulator
//   kernel 1: repack input_weights int32 -> int16 into __device__ scratch (21 MB)
//   kernel 2: per-sample gather-accumulate (warp/sample) + FC1/FC2 + atomicAdd
//   kernel 3: finalize floor_div(s + out_b, 16) -> float32 output
//
// Inputs (metadata order, ALL int32 on device):
//  0 piece_positions (B,64,10)  1 king_positions (B,2)
//  2 input_weights (64,641,256) 3 input_bias (256)
//  4 w1 (32,512)  5 b1 (32)  6 w2 (32,32)  7 b2 (32)  8 out_w (32)  9 out_b (1)
// out: float32 (1)

#define W_ELEMS (64 * 641 * 256)   // 10,502,144

__device__ short g_W16[W_ELEMS];   // repacked weight table (21 MB)
__device__ int   g_total;

__global__ void hx_zero() { g_total = 0; }

// int32 -> int16 repack, 4 elems/thread. grid = W_ELEMS/4/256 = 10256 blocks.
__global__ void __launch_bounds__(256) hx_repack(const int* __restrict__ W32) {
    const int idx = blockIdx.x * blockDim.x + threadIdx.x;
    if (idx < W_ELEMS / 4) {
        int4 v = ((const int4*)W32)[idx];
        ((short4*)g_W16)[idx] = make_short4((short)v.x, (short)v.y, (short)v.z, (short)v.w);
    }
}

__global__ void __launch_bounds__(256, 1) hx_main(
    const int* __restrict__ pp,      // 0/1 per feature
    const int* __restrict__ kings,
    const int* __restrict__ bias,    // int16 values widened to int32
    const int* __restrict__ w1,      // int8 values widened to int32
    const int* __restrict__ b1,
    const int* __restrict__ w2,
    const int* __restrict__ b2,
    const int* __restrict__ ow,
    int B)
{
    __shared__ unsigned short s_list[8][640];
    __shared__ unsigned int   s_x[8][64];     // clipped int8 activations, packed
    __shared__ int            s_x1[8][32];
    __shared__ int            s_wsum[8];
    __shared__ unsigned int   s_w1[32 * 128]; // w1 repacked to dp4a form (16 KB)

    const int warp = threadIdx.x >> 5;
    const int lane = threadIdx.x & 31;
    const int b    = blockIdx.x * 8 + warp;
    const bool active = (b < B);

    // ---- repack w1 (int32 values in [-128,127]) into packed int8 words ----
    for (int t = threadIdx.x; t < 32 * 128; t += 256) {
        const int* p = w1 + t * 4;
        s_w1[t] = (unsigned)(p[0] & 0xff) | ((unsigned)(p[1] & 0xff) << 8) |
                  ((unsigned)(p[2] & 0xff) << 16) | ((unsigned)p[3] << 24);
    }
    __syncthreads();

    int contrib = 0;

    if (active) {
        // ---- compacted active-feature list (ballot compaction), pp is int32 ----
        const int* ppb = pp + (size_t)b * 640;
        int n = 0;
        #pragma unroll
        for (int c = 0; c < 20; c++) {
            const int f = c * 32 + lane;
            const int v = ppb[f];
            const unsigned m = __ballot_sync(0xffffffffu, v != 0);
            if (v) s_list[warp][n + __popc(m & ((1u << lane) - 1u))] = (unsigned short)f;
            n += __popc(m);
        }
        __syncwarp();

        // ---- accumulate rows of both king tables in packed int16 (wraparound) ----
        const int kw = kings[2 * b + 0];
        const int kb = kings[2 * b + 1];
        const char* tw = (const char*)g_W16 + (size_t)kw * (641 * 512);
        const char* tb = (const char*)g_W16 + (size_t)kb * (641 * 512);
        const int off = lane * 16;   // lane covers dims [lane*8, lane*8+8)

        // init: per-king bias rows (row 640) + input_bias (int32 -> halfword pack)
        uint4 rw = *(const uint4*)(tw + 640 * 512 + off);
        uint4 rb = *(const uint4*)(tb + 640 * 512 + off);
        int4 bA = ((const int4*)bias)[lane * 2 + 0];
        int4 bB = ((const int4*)bias)[lane * 2 + 1];
        const unsigned bi0 = (unsigned)(bA.x & 0xffff) | ((unsigned)bA.y << 16);
        const unsigned bi1 = (unsigned)(bA.z & 0xffff) | ((unsigned)bA.w << 16);
        const unsigned bi2 = (unsigned)(bB.x & 0xffff) | ((unsigned)bB.y << 16);
        const unsigned bi3 = (unsigned)(bB.z & 0xffff) | ((unsigned)bB.w << 16);
        unsigned acc0 = __vadd2(__vadd2(rw.x, rb.x), bi0);
        unsigned acc1 = __vadd2(__vadd2(rw.y, rb.y), bi1);
        unsigned acc2 = __vadd2(__vadd2(rw.z, rb.z), bi2);
        unsigned acc3 = __vadd2(__vadd2(rw.w, rb.w), bi3);

        // main loop: 4 features/step -> 8 independent LDG.128 in flight per warp
        int i = 0;
        while (i < n) {
            uint4 r[8];
            int cnt = n - i; if (cnt > 4) cnt = 4;
            #pragma unroll
            for (int j = 0; j < 4; j++) {
                if (j < cnt) {
                    const int f = (int)s_list[warp][i + j];
                    r[2 * j + 0] = *(const uint4*)(tw + f * 512 + off);
                    r[2 * j + 1] = *(const uint4*)(tb + f * 512 + off);
                }
            }
            #pragma unroll
            for (int j = 0; j < 4; j++) {
                if (j < cnt) {
                    acc0 = __vadd2(__vadd2(acc0, r[2 * j].x), r[2 * j + 1].x);
                    acc1 = __vadd2(__vadd2(acc1, r[2 * j].y), r[2 * j + 1].y);
                    acc2 = __vadd2(__vadd2(acc2, r[2 * j].z), r[2 * j + 1].z);
                    acc3 = __vadd2(__vadd2(acc3, r[2 * j].w), r[2 * j + 1].w);
                }
            }
            i += cnt;
        }

        // ---- clip int16 -> [0,127], pack 8 int8 into 2 words ----
        unsigned accs[4] = {acc0, acc1, acc2, acc3};
        int c8[8];
        #pragma unroll
        for (int k = 0; k < 4; k++) {
            int lo = (int)(short)(accs[k] & 0xffffu);
            int hi = (int)(short)(accs[k] >> 16);
            c8[2 * k + 0] = min(max(lo, 0), 127);
            c8[2 * k + 1] = min(max(hi, 0), 127);
        }
        s_x[warp][lane * 2 + 0] = (unsigned)c8[0] | ((unsigned)c8[1] << 8) |
                                  ((unsigned)c8[2] << 16) | ((unsigned)c8[3] << 24);
        s_x[warp][lane * 2 + 1] = (unsigned)c8[4] | ((unsigned)c8[5] << 8) |
                                  ((unsigned)c8[6] << 16) | ((unsigned)c8[7] << 24);
        __syncwarp();

        // ---- FC1: lane = output unit; x512 = [x, x] -> both w1 halves ----
        const unsigned* row = s_w1 + lane * 128;
        int a1 = b1[lane];
        #pragma unroll 8
        for (int j = 0; j < 64; j++) {
            const int xv = (int)s_x[warp][j];
            a1 = __dp4a(xv, (int)row[j],      a1);
            a1 = __dp4a(xv, (int)row[64 + j], a1);
        }
        a1 >>= 6;                                  // floor_divide 64
        a1 = min(max(a1, 0), 127);
        s_x1[warp][lane] = a1;
        __syncwarp();

        // ---- FC2 (w2 int32 values, tiny, L1-resident) ----
        int a2 = b2[lane];
        #pragma unroll 8
        for (int o = 0; o < 32; o++)
            a2 += s_x1[warp][o] * w2[lane * 32 + o];
        a2 >>= 6;
        a2 = min(max(a2, 0), 127);

        // ---- output dot + warp reduce ----
        contrib = a2 * ow[lane];
        #pragma unroll
        for (int s = 16; s; s >>= 1)
            contrib += __shfl_xor_sync(0xffffffffu, contrib, s);
    }

    if (lane == 0) s_wsum[warp] = contrib;
    __syncthreads();
    if (threadIdx.x == 0) {
        int t = 0;
        #pragma unroll
        for (int w = 0; w < 8; w++) t += s_wsum[w];
        atomicAdd(&g_total, t);
    }
}

__global__ void hx_final(const int* __restrict__ ob, float* __restrict__ out) {
    int v = (g_total + ob[0]) >> 4;   // arithmetic shift = floor_divide by 16
    out[0] = (float)v;
}

extern "C" void kernel_launch(void* const* d_in, const int* in_sizes, int n_in,
                              void* d_out, int out_size) {
    const int B = in_sizes[0] / 640;
    hx_zero<<<1, 1>>>();
    hx_repack<<<W_ELEMS / 4 / 256, 256>>>((const int*)d_in[2]);
    hx_main<<<(B + 7) / 8, 256>>>(
        (const int*)d_in[0],
        (const int*)d_in[1],
        (const int*)d_in[3],
        (const int*)d_in[4],
        (const int*)d_in[5],
        (const int*)d_in[6],
        (const int*)d_in[7],
        (const int*)d_in[8],
        B);
    hx_final<<<1, 1>>>((const int*)d_in[9], (float*)d_out);
}

// round 4
// speedup vs baseline: 1.0496x; 1.0496x over previous
#include <cuda_runtime.h>
#include <cstdint>

// NNUE HalfKP forward — king-grouped formulation.
//   kernel 1 (prep):   feature bitmasks per sample; bucket (sample,side) pairs by king;
//                      zero accumulators. (block 0 does the bucketing)
//   kernel 2 (phaseA): grid (64 kings x 4 row-quarters). Stage 160 rows of the king's
//                      int32 table into SMEM as int16; each warp accumulates packed-int16
//                      partial sums for its pairs; store to g_part.
//   kernel 3 (phaseB): per sample: combine 4x2 partials + king bias rows + input_bias
//                      (mod 2^16 == ref astype(int16)), clip, FC1/FC2, output dot,
//                      atomicAdd; last block finalizes floor_div(s+out_b,16) as float.
//
// Inputs (ALL integers widened to int32 by the harness):
//  0 piece_positions (B,640)  1 king_positions (B,2)  2 input_weights (64,641,256)
//  3 input_bias (256)  4 w1 (32,512)  5 b1 (32)  6 w2 (32,32)  7 b2 (32)
//  8 out_w (32)  9 out_b (1)        out: float32 (1)

#define MAXS   4096                   // max samples supported
#define MAXP   (2 * MAXS)             // max (sample,side) pairs
#define QROWS  160                    // rows per quarter (4 * 160 = 640)
#define TILE_BYTES (QROWS * 512)      // 80 KB dynamic SMEM

__device__ unsigned g_mask[MAXS][20];      // 640-bit occupancy per sample
__device__ int      g_cnt[64];             // pairs per king
__device__ int      g_bucket[64][MAXP];    // pair ids per king
__device__ uint4    g_part[4][MAXP * 32];  // packed-int16 partial sums (16 MB)
__device__ int      g_total;
__device__ int      g_done;

// ---------------- prep: masks + king buckets + zeroing ----------------
__global__ void __launch_bounds__(256) hx_prep(
    const int* __restrict__ pp, const int* __restrict__ kings, int B)
{
    const int warp = threadIdx.x >> 5;
    const int lane = threadIdx.x & 31;
    const int s = blockIdx.x * 8 + warp;
    if (s < B) {
        const int* ppb = pp + (size_t)s * 640;
        #pragma unroll
        for (int c = 0; c < 20; c++) {
            const unsigned m = __ballot_sync(0xffffffffu, ppb[c * 32 + lane] != 0);
            if (lane == 0) g_mask[s][c] = m;
        }
    }
    if (blockIdx.x == 0) {
        if (threadIdx.x < 64) g_cnt[threadIdx.x] = 0;
        if (threadIdx.x == 0) { g_total = 0; g_done = 0; }
        __syncthreads();
        const int P = 2 * B;
        for (int p = threadIdx.x; p < P; p += 256) {
            const int k = kings[p];
            const int slot = atomicAdd(&g_cnt[k], 1);
            if (slot < MAXP) g_bucket[k][slot] = p;
        }
    }
}

// ---------------- phase A: SMEM-staged gather-accumulate ----------------
__global__ void __launch_bounds__(256, 2) hx_phaseA(const int* __restrict__ W32)
{
    extern __shared__ short tile[];            // [QROWS][256] int16
    const int k = blockIdx.x;
    const int q = blockIdx.y;
    const int cnt = g_cnt[k];
    if (cnt == 0) return;

    // stage + narrow: int32 table rows [q*160, q*160+160) -> int16 SMEM
    const int4* src = (const int4*)(W32 + ((size_t)k * 641 + (size_t)q * QROWS) * 256);
    short4* dst = (short4*)tile;
    #pragma unroll 4
    for (int i = threadIdx.x; i < QROWS * 256 / 4; i += 256) {
        const int4 v = src[i];
        dst[i] = make_short4((short)v.x, (short)v.y, (short)v.z, (short)v.w);
    }
    __syncthreads();

    const int warp = threadIdx.x >> 5;
    const int lane = threadIdx.x & 31;
    const char* base = (const char*)tile + lane * 16;   // lane covers 8 dims

    for (int pi = warp; pi < cnt; pi += 8) {
        const int p = g_bucket[k][pi];
        const unsigned* mw = g_mask[p >> 1] + q * 5;    // 160 bits = 5 words
        unsigned acc0 = 0, acc1 = 0, acc2 = 0, acc3 = 0;
        #pragma unroll
        for (int w = 0; w < 5; w++) {
            unsigned m = mw[w];
            const char* wbase = base + (w << 14);       // w*32 rows * 512 B
            while (m) {
                const int bit = __ffs(m) - 1;
                m &= m - 1;
                const uint4 r = *(const uint4*)(wbase + (bit << 9));
                acc0 = __vadd2(acc0, r.x);
                acc1 = __vadd2(acc1, r.y);
                acc2 = __vadd2(acc2, r.z);
                acc3 = __vadd2(acc3, r.w);
            }
        }
        g_part[q][p * 32 + lane] = make_uint4(acc0, acc1, acc2, acc3);
    }
}

// ---------------- phase B: combine + FC + finalize ----------------
__global__ void __launch_bounds__(256, 1) hx_phaseB(
    const int* __restrict__ W32,
    const int* __restrict__ kings,
    const int* __restrict__ bias,
    const int* __restrict__ w1,
    const int* __restrict__ b1,
    const int* __restrict__ w2,
    const int* __restrict__ b2,
    const int* __restrict__ ow,
    const int* __restrict__ ob,
    float* __restrict__ out,
    int B, int nblocks)
{
    __shared__ unsigned s_w1[32 * 128];   // dp4a-packed w1 (16 KB)
    __shared__ unsigned s_x[8][64];
    __shared__ int      s_x1[8][32];
    __shared__ int      s_wsum[8];

    for (int t = threadIdx.x; t < 32 * 128; t += 256) {
        const int* p = w1 + t * 4;
        s_w1[t] = (unsigned)(p[0] & 0xff) | ((unsigned)(p[1] & 0xff) << 8) |
                  ((unsigned)(p[2] & 0xff) << 16) | ((unsigned)p[3] << 24);
    }
    __syncthreads();

    const int warp = threadIdx.x >> 5;
    const int lane = threadIdx.x & 31;
    const int s = blockIdx.x * 8 + warp;
    int contrib = 0;

    if (s < B) {
        // combine 4 quarters x 2 sides (packed int16, mod 2^16 exact)
        unsigned a0 = 0, a1 = 0, a2 = 0, a3 = 0;
        #pragma unroll
        for (int q = 0; q < 4; q++) {
            #pragma unroll
            for (int side = 0; side < 2; side++) {
                const uint4 r = g_part[q][(2 * s + side) * 32 + lane];
                a0 = __vadd2(a0, r.x); a1 = __vadd2(a1, r.y);
                a2 = __vadd2(a2, r.z); a3 = __vadd2(a3, r.w);
            }
        }
        // per-king bias rows (row 640) from the int32 table
        #pragma unroll
        for (int side = 0; side < 2; side++) {
            const int k = kings[2 * s + side];
            const int4* br = (const int4*)(W32 + ((size_t)k * 641 + 640) * 256 + lane * 8);
            const int4 u = br[0], v = br[1];
            a0 = __vadd2(a0, (unsigned)(u.x & 0xffff) | ((unsigned)u.y << 16));
            a1 = __vadd2(a1, (unsigned)(u.z & 0xffff) | ((unsigned)u.w << 16));
            a2 = __vadd2(a2, (unsigned)(v.x & 0xffff) | ((unsigned)v.y << 16));
            a3 = __vadd2(a3, (unsigned)(v.z & 0xffff) | ((unsigned)v.w << 16));
        }
        // input_bias
        {
            const int4 bA = ((const int4*)bias)[lane * 2 + 0];
            const int4 bB = ((const int4*)bias)[lane * 2 + 1];
            a0 = __vadd2(a0, (unsigned)(bA.x & 0xffff) | ((unsigned)bA.y << 16));
            a1 = __vadd2(a1, (unsigned)(bA.z & 0xffff) | ((unsigned)bA.w << 16));
            a2 = __vadd2(a2, (unsigned)(bB.x & 0xffff) | ((unsigned)bB.y << 16));
            a3 = __vadd2(a3, (unsigned)(bB.z & 0xffff) | ((unsigned)bB.w << 16));
        }

        // clip int16 -> [0,127], pack 8 int8 into 2 words
        unsigned accs[4] = {a0, a1, a2, a3};
        int c8[8];
        #pragma unroll
        for (int kk = 0; kk < 4; kk++) {
            int lo = (int)(short)(accs[kk] & 0xffffu);
            int hi = (int)(short)(accs[kk] >> 16);
            c8[2 * kk + 0] = min(max(lo, 0), 127);
            c8[2 * kk + 1] = min(max(hi, 0), 127);
        }
        s_x[warp][lane * 2 + 0] = (unsigned)c8[0] | ((unsigned)c8[1] << 8) |
                                  ((unsigned)c8[2] << 16) | ((unsigned)c8[3] << 24);
        s_x[warp][lane * 2 + 1] = (unsigned)c8[4] | ((unsigned)c8[5] << 8) |
                                  ((unsigned)c8[6] << 16) | ((unsigned)c8[7] << 24);
        __syncwarp();

        // FC1: lane = output unit; x512 = [x, x]
        const unsigned* row = s_w1 + lane * 128;
        int v1 = b1[lane];
        #pragma unroll 8
        for (int j = 0; j < 64; j++) {
            const int xv = (int)s_x[warp][j];
            v1 = __dp4a(xv, (int)row[j],      v1);
            v1 = __dp4a(xv, (int)row[64 + j], v1);
        }
        v1 >>= 6;
        v1 = min(max(v1, 0), 127);
        s_x1[warp][lane] = v1;
        __syncwarp();

        // FC2
        int v2 = b2[lane];
        #pragma unroll 8
        for (int o = 0; o < 32; o++)
            v2 += s_x1[warp][o] * w2[lane * 32 + o];
        v2 >>= 6;
        v2 = min(max(v2, 0), 127);

        contrib = v2 * ow[lane];
        #pragma unroll
        for (int sh = 16; sh; sh >>= 1)
            contrib += __shfl_xor_sync(0xffffffffu, contrib, sh);
    }

    if (lane == 0) s_wsum[warp] = contrib;
    __syncthreads();
    if (threadIdx.x == 0) {
        int t = 0;
        #pragma unroll
        for (int w = 0; w < 8; w++) t += s_wsum[w];
        atomicAdd(&g_total, t);
        __threadfence();
        if (atomicAdd(&g_done, 1) == nblocks - 1) {
            const int tot = atomicAdd(&g_total, 0);
            out[0] = (float)((tot + ob[0]) >> 4);
        }
    }
}

extern "C" void kernel_launch(void* const* d_in, const int* in_sizes, int n_in,
                              void* d_out, int out_size) {
    const int B = in_sizes[0] / 640;
    const int sblocks = (B + 7) / 8;

    static bool attr_set = false;
    if (!attr_set) {
        cudaFuncSetAttribute(hx_phaseA,
            cudaFuncAttributeMaxDynamicSharedMemorySize, TILE_BYTES);
        attr_set = true;
    }

    hx_prep<<<sblocks, 256>>>((const int*)d_in[0], (const int*)d_in[1], B);
    hx_phaseA<<<dim3(64, 4), 256, TILE_BYTES>>>((const int*)d_in[2]);
    hx_phaseB<<<sblocks, 256>>>(
        (const int*)d_in[2],
        (const int*)d_in[1],
        (const int*)d_in[3],
        (const int*)d_in[4],
        (const int*)d_in[5],
        (const int*)d_in[6],
        (const int*)d_in[7],
        (const int*)d_in[8],
        (const int*)d_in[9],
        (float*)d_out,
        B, sblocks);
}

// round 5
// speedup vs baseline: 1.4102x; 1.3436x over previous
#include <cuda_runtime.h>
#include <cstdint>

// NNUE HalfKP forward — king-grouped, 2-kernel formulation.
//   phaseA: grid (64 kings x 10 row-tenths). Each block: scan kings[] to build its
//           bucket (SMEM), stage 64 table rows int32->int16 in SMEM, then per pair:
//           ballot occupancy mask on the fly, ffs-walk set bits, accumulate packed
//           int16 partial sums -> g_part.  Block (0,0) zeroes scalar accumulators.
//   phaseB: per sample: combine 10x2 partials + 2 king bias rows + input_bias
//           (mod 2^16 == ref astype(int16)), clip, FC1/FC2, output dot, atomicAdd;
//           last block writes floor_div(total + out_b, 16) as float32.
//
// Inputs (ALL integers widened to int32 by the harness):
//  0 piece_positions (B,640)  1 king_positions (B,2)  2 input_weights (64,641,256)
//  3 input_bias (256)  4 w1 (32,512)  5 b1 (32)  6 w2 (32,32)  7 b2 (32)
//  8 out_w (32)  9 out_b (1)        out: float32 (1)

#define NQ      10                 // row tenths
#define QR      64                 // rows per tenth
#define MAXP    2048               // max (sample,side) pairs (B <= 1024)

__device__ uint4 g_part[NQ][MAXP * 32];   // packed-int16 partial sums (10 MB)
__device__ int   g_total;
__device__ int   g_done;

// ---------------- phase A ----------------
__global__ void __launch_bounds__(256) hx_phaseA(
    const int* __restrict__ W32,
    const int* __restrict__ pp,
    const int* __restrict__ kings,
    int B)
{
    __shared__ short s_tile[QR * 256];    // 32 KB, rows [q*64, q*64+64)
    __shared__ int   s_bucket[MAXP];      // 8 KB
    __shared__ int   s_cnt;

    const int k = blockIdx.x;
    const int q = blockIdx.y;

    if (k == 0 && q == 0 && threadIdx.x == 0) { g_total = 0; g_done = 0; }
    if (threadIdx.x == 0) s_cnt = 0;
    __syncthreads();

    // build bucket: scan all (sample,side) pairs for king == k
    const int P = 2 * B;
    for (int i = threadIdx.x; i < P; i += 256)
        if (kings[i] == k) {
            const int slot = atomicAdd(&s_cnt, 1);
            if (slot < MAXP) s_bucket[slot] = i;
        }

    // stage + narrow: rows [q*64, q*64+64) of king k's int32 table -> int16 SMEM
    {
        const int4* src = (const int4*)(W32 + ((size_t)k * 641 + (size_t)q * QR) * 256);
        short4* dst = (short4*)s_tile;
        #pragma unroll 4
        for (int i = threadIdx.x; i < QR * 256 / 4; i += 256) {
            const int4 v = src[i];
            dst[i] = make_short4((short)v.x, (short)v.y, (short)v.z, (short)v.w);
        }
    }
    __syncthreads();

    const int cnt  = min(s_cnt, MAXP);
    if (cnt == 0) return;
    const int warp = threadIdx.x >> 5;
    const int lane = threadIdx.x & 31;
    const char* base = (const char*)s_tile + lane * 16;   // lane covers 8 dims

    for (int pi = warp; pi < cnt; pi += 8) {
        const int p = s_bucket[pi];
        const int s = p >> 1;
        // occupancy masks for this tenth, built on the fly (coalesced loads + ballot)
        const int* ppq = pp + (size_t)s * 640 + q * QR;
        const unsigned m0 = __ballot_sync(0xffffffffu, ppq[lane]      != 0);
        const unsigned m1 = __ballot_sync(0xffffffffu, ppq[32 + lane] != 0);

        unsigned acc0 = 0, acc1 = 0, acc2 = 0, acc3 = 0;
        unsigned m = m0;
        while (m) {
            const int bit = __ffs(m) - 1;
            m &= m - 1;
            const uint4 r = *(const uint4*)(base + (bit << 9));
            acc0 = __vadd2(acc0, r.x);
            acc1 = __vadd2(acc1, r.y);
            acc2 = __vadd2(acc2, r.z);
            acc3 = __vadd2(acc3, r.w);
        }
        m = m1;
        const char* base1 = base + (32 << 9);
        while (m) {
            const int bit = __ffs(m) - 1;
            m &= m - 1;
            const uint4 r = *(const uint4*)(base1 + (bit << 9));
            acc0 = __vadd2(acc0, r.x);
            acc1 = __vadd2(acc1, r.y);
            acc2 = __vadd2(acc2, r.z);
            acc3 = __vadd2(acc3, r.w);
        }
        g_part[q][p * 32 + lane] = make_uint4(acc0, acc1, acc2, acc3);
    }
}

// ---------------- phase B: combine + FC + finalize ----------------
__global__ void __launch_bounds__(256, 1) hx_phaseB(
    const int* __restrict__ W32,
    const int* __restrict__ kings,
    const int* __restrict__ bias,
    const int* __restrict__ w1,
    const int* __restrict__ b1,
    const int* __restrict__ w2,
    const int* __restrict__ b2,
    const int* __restrict__ ow,
    const int* __restrict__ ob,
    float* __restrict__ out,
    int B, int nblocks)
{
    __shared__ unsigned s_w1[32 * 128];   // dp4a-packed w1 (16 KB)
    __shared__ unsigned s_x[8][64];
    __shared__ int      s_x1[8][32];
    __shared__ int      s_wsum[8];

    for (int t = threadIdx.x; t < 32 * 128; t += 256) {
        const int* p = w1 + t * 4;
        s_w1[t] = (unsigned)(p[0] & 0xff) | ((unsigned)(p[1] & 0xff) << 8) |
                  ((unsigned)(p[2] & 0xff) << 16) | ((unsigned)p[3] << 24);
    }
    __syncthreads();

    const int warp = threadIdx.x >> 5;
    const int lane = threadIdx.x & 31;
    const int s = blockIdx.x * 8 + warp;
    int contrib = 0;

    if (s < B) {
        // combine NQ tenths x 2 sides (packed int16, mod 2^16 exact)
        unsigned a0 = 0, a1 = 0, a2 = 0, a3 = 0;
        #pragma unroll
        for (int q = 0; q < NQ; q++) {
            #pragma unroll
            for (int side = 0; side < 2; side++) {
                const uint4 r = g_part[q][(2 * s + side) * 32 + lane];
                a0 = __vadd2(a0, r.x); a1 = __vadd2(a1, r.y);
                a2 = __vadd2(a2, r.z); a3 = __vadd2(a3, r.w);
            }
        }
        // per-king bias rows (row 640) from the int32 table
        #pragma unroll
        for (int side = 0; side < 2; side++) {
            const int k = kings[2 * s + side];
            const int4* br = (const int4*)(W32 + ((size_t)k * 641 + 640) * 256 + lane * 8);
            const int4 u = br[0], v = br[1];
            a0 = __vadd2(a0, (unsigned)(u.x & 0xffff) | ((unsigned)u.y << 16));
            a1 = __vadd2(a1, (unsigned)(u.z & 0xffff) | ((unsigned)u.w << 16));
            a2 = __vadd2(a2, (unsigned)(v.x & 0xffff) | ((unsigned)v.y << 16));
            a3 = __vadd2(a3, (unsigned)(v.z & 0xffff) | ((unsigned)v.w << 16));
        }
        // input_bias
        {
            const int4 bA = ((const int4*)bias)[lane * 2 + 0];
            const int4 bB = ((const int4*)bias)[lane * 2 + 1];
            a0 = __vadd2(a0, (unsigned)(bA.x & 0xffff) | ((unsigned)bA.y << 16));
            a1 = __vadd2(a1, (unsigned)(bA.z & 0xffff) | ((unsigned)bA.w << 16));
            a2 = __vadd2(a2, (unsigned)(bB.x & 0xffff) | ((unsigned)bB.y << 16));
            a3 = __vadd2(a3, (unsigned)(bB.z & 0xffff) | ((unsigned)bB.w << 16));
        }

        // clip int16 -> [0,127], pack 8 int8 into 2 words
        unsigned accs[4] = {a0, a1, a2, a3};
        int c8[8];
        #pragma unroll
        for (int kk = 0; kk < 4; kk++) {
            int lo = (int)(short)(accs[kk] & 0xffffu);
            int hi = (int)(short)(accs[kk] >> 16);
            c8[2 * kk + 0] = min(max(lo, 0), 127);
            c8[2 * kk + 1] = min(max(hi, 0), 127);
        }
        s_x[warp][lane * 2 + 0] = (unsigned)c8[0] | ((unsigned)c8[1] << 8) |
                                  ((unsigned)c8[2] << 16) | ((unsigned)c8[3] << 24);
        s_x[warp][lane * 2 + 1] = (unsigned)c8[4] | ((unsigned)c8[5] << 8) |
                                  ((unsigned)c8[6] << 16) | ((unsigned)c8[7] << 24);
        __syncwarp();

        // FC1: lane = output unit; x512 = [x, x]
        const unsigned* row = s_w1 + lane * 128;
        int v1 = b1[lane];
        #pragma unroll 8
        for (int j = 0; j < 64; j++) {
            const int xv = (int)s_x[warp][j];
            v1 = __dp4a(xv, (int)row[j],      v1);
            v1 = __dp4a(xv, (int)row[64 + j], v1);
        }
        v1 >>= 6;
        v1 = min(max(v1, 0), 127);
        s_x1[warp][lane] = v1;
        __syncwarp();

        // FC2
        int v2 = b2[lane];
        #pragma unroll 8
        for (int o = 0; o < 32; o++)
            v2 += s_x1[warp][o] * w2[lane * 32 + o];
        v2 >>= 6;
        v2 = min(max(v2, 0), 127);

        contrib = v2 * ow[lane];
        #pragma unroll
        for (int sh = 16; sh; sh >>= 1)
            contrib += __shfl_xor_sync(0xffffffffu, contrib, sh);
    }

    if (lane == 0) s_wsum[warp] = contrib;
    __syncthreads();
    if (threadIdx.x == 0) {
        int t = 0;
        #pragma unroll
        for (int w = 0; w < 8; w++) t += s_wsum[w];
        atomicAdd(&g_total, t);
        __threadfence();
        if (atomicAdd(&g_done, 1) == nblocks - 1) {
            const int tot = atomicAdd(&g_total, 0);
            out[0] = (float)((tot + ob[0]) >> 4);
        }
    }
}

extern "C" void kernel_launch(void* const* d_in, const int* in_sizes, int n_in,
                              void* d_out, int out_size) {
    const int B = in_sizes[0] / 640;
    const int sblocks = (B + 7) / 8;

    hx_phaseA<<<dim3(64, NQ), 256>>>(
        (const int*)d_in[2], (const int*)d_in[0], (const int*)d_in[1], B);
    hx_phaseB<<<sblocks, 256>>>(
        (const int*)d_in[2],
        (const int*)d_in[1],
        (const int*)d_in[3],
        (const int*)d_in[4],
        (const int*)d_in[5],
        (const int*)d_in[6],
        (const int*)d_in[7],
        (const int*)d_in[8],
        (const int*)d_in[9],
        (float*)d_out,
        B, sblocks);
}

// round 6
// speedup vs baseline: 1.6581x; 1.1757x over previous
#include <cuda_runtime.h>
#include <cstdint>

// NNUE HalfKP forward — king-grouped, 2-kernel formulation.
//   phaseA: grid (64 kings x 10 row-tenths). Each block: scan kings[] to build its
//           bucket (SMEM), stage 64 table rows int32->int16 in SMEM, then per pair:
//           ballot occupancy mask on the fly, ffs-walk set bits, accumulate packed
//           int16 partial sums -> g_part.  Block (0,0) zeroes scalar accumulators.
//   phaseB: per sample: combine 10x2 partials + 2 king bias rows + input_bias
//           (mod 2^16 == ref astype(int16)), clip, FC1/FC2 (bank-conflict-free
//           transposed SMEM weights), output dot, atomicAdd; last block writes
//           floor_div(total + out_b, 16) as float32.
//
// Inputs (ALL integers widened to int32 by the harness):
//  0 piece_positions (B,640)  1 king_positions (B,2)  2 input_weights (64,641,256)
//  3 input_bias (256)  4 w1 (32,512)  5 b1 (32)  6 w2 (32,32)  7 b2 (32)
//  8 out_w (32)  9 out_b (1)        out: float32 (1)

#define NQ      10                 // row tenths
#define QR      64                 // rows per tenth
#define MAXP    2048               // max (sample,side) pairs (B <= 1024)

__device__ uint4 g_part[NQ][MAXP * 32];   // packed-int16 partial sums (10 MB)
__device__ int   g_total;
__device__ int   g_done;

// ---------------- phase A ----------------
__global__ void __launch_bounds__(256) hx_phaseA(
    const int* __restrict__ W32,
    const int* __restrict__ pp,
    const int* __restrict__ kings,
    int B)
{
    __shared__ short s_tile[QR * 256];    // 32 KB, rows [q*64, q*64+64)
    __shared__ int   s_bucket[MAXP];      // 8 KB
    __shared__ int   s_cnt;

    const int k = blockIdx.x;
    const int q = blockIdx.y;

    if (k == 0 && q == 0 && threadIdx.x == 0) { g_total = 0; g_done = 0; }
    if (threadIdx.x == 0) s_cnt = 0;
    __syncthreads();

    // build bucket: scan all (sample,side) pairs for king == k
    const int P = 2 * B;
    for (int i = threadIdx.x; i < P; i += 256)
        if (kings[i] == k) {
            const int slot = atomicAdd(&s_cnt, 1);
            if (slot < MAXP) s_bucket[slot] = i;
        }

    // stage + narrow: rows [q*64, q*64+64) of king k's int32 table -> int16 SMEM
    {
        const int4* src = (const int4*)(W32 + ((size_t)k * 641 + (size_t)q * QR) * 256);
        short4* dst = (short4*)s_tile;
        #pragma unroll 4
        for (int i = threadIdx.x; i < QR * 256 / 4; i += 256) {
            const int4 v = src[i];
            dst[i] = make_short4((short)v.x, (short)v.y, (short)v.z, (short)v.w);
        }
    }
    __syncthreads();

    const int cnt  = min(s_cnt, MAXP);
    if (cnt == 0) return;
    const int warp = threadIdx.x >> 5;
    const int lane = threadIdx.x & 31;
    const char* base = (const char*)s_tile + lane * 16;   // lane covers 8 dims

    for (int pi = warp; pi < cnt; pi += 8) {
        const int p = s_bucket[pi];
        const int s = p >> 1;
        // occupancy masks for this tenth, built on the fly (coalesced loads + ballot)
        const int* ppq = pp + (size_t)s * 640 + q * QR;
        const unsigned m0 = __ballot_sync(0xffffffffu, ppq[lane]      != 0);
        const unsigned m1 = __ballot_sync(0xffffffffu, ppq[32 + lane] != 0);

        unsigned acc0 = 0, acc1 = 0, acc2 = 0, acc3 = 0;
        unsigned m = m0;
        while (m) {
            const int bit = __ffs(m) - 1;
            m &= m - 1;
            const uint4 r = *(const uint4*)(base + (bit << 9));
            acc0 = __vadd2(acc0, r.x);
            acc1 = __vadd2(acc1, r.y);
            acc2 = __vadd2(acc2, r.z);
            acc3 = __vadd2(acc3, r.w);
        }
        m = m1;
        const char* base1 = base + (32 << 9);
        while (m) {
            const int bit = __ffs(m) - 1;
            m &= m - 1;
            const uint4 r = *(const uint4*)(base1 + (bit << 9));
            acc0 = __vadd2(acc0, r.x);
            acc1 = __vadd2(acc1, r.y);
            acc2 = __vadd2(acc2, r.z);
            acc3 = __vadd2(acc3, r.w);
        }
        g_part[q][p * 32 + lane] = make_uint4(acc0, acc1, acc2, acc3);
    }
}

// ---------------- phase B: combine + FC + finalize ----------------
__global__ void __launch_bounds__(256, 1) hx_phaseB(
    const int* __restrict__ W32,
    const int* __restrict__ kings,
    const int* __restrict__ bias,
    const int* __restrict__ w1,
    const int* __restrict__ b1,
    const int* __restrict__ w2,
    const int* __restrict__ b2,
    const int* __restrict__ ow,
    const int* __restrict__ ob,
    float* __restrict__ out,
    int B, int nblocks)
{
    // TRANSPOSED weight layouts: s_w1[j*32 + out] so FC1's per-lane (=per-out)
    // LDS hits 32 distinct banks (old out-major layout was a 32-way conflict).
    __shared__ unsigned s_w1[128 * 32];   // 16 KB, j-major dp4a-packed w1
    __shared__ int      s_w2[32 * 32];    // 4 KB,  in-major w2
    __shared__ unsigned s_x[8][64];
    __shared__ int      s_x1[8][32];
    __shared__ int      s_wsum[8];

    for (int t = threadIdx.x; t < 32 * 128; t += 256) {
        const int o = t >> 7;           // output unit
        const int j = t & 127;          // packed-word index
        const int* p = w1 + t * 4;      // == (o*128 + j)*4 : coalesced
        s_w1[j * 32 + o] = (unsigned)(p[0] & 0xff) | ((unsigned)(p[1] & 0xff) << 8) |
                           ((unsigned)(p[2] & 0xff) << 16) | ((unsigned)p[3] << 24);
    }
    for (int t = threadIdx.x; t < 32 * 32; t += 256)
        s_w2[t] = w2[(t & 31) * 32 + (t >> 5)];   // s_w2[in*32 + out]
    __syncthreads();

    const int warp = threadIdx.x >> 5;
    const int lane = threadIdx.x & 31;
    const int s = blockIdx.x * 8 + warp;
    int contrib = 0;

    if (s < B) {
        // combine NQ tenths x 2 sides (packed int16, mod 2^16 exact)
        unsigned a0 = 0, a1 = 0, a2 = 0, a3 = 0;
        #pragma unroll
        for (int q = 0; q < NQ; q++) {
            #pragma unroll
            for (int side = 0; side < 2; side++) {
                const uint4 r = g_part[q][(2 * s + side) * 32 + lane];
                a0 = __vadd2(a0, r.x); a1 = __vadd2(a1, r.y);
                a2 = __vadd2(a2, r.z); a3 = __vadd2(a3, r.w);
            }
        }
        // per-king bias rows (row 640) from the int32 table
        #pragma unroll
        for (int side = 0; side < 2; side++) {
            const int k = kings[2 * s + side];
            const int4* br = (const int4*)(W32 + ((size_t)k * 641 + 640) * 256 + lane * 8);
            const int4 u = br[0], v = br[1];
            a0 = __vadd2(a0, (unsigned)(u.x & 0xffff) | ((unsigned)u.y << 16));
            a1 = __vadd2(a1, (unsigned)(u.z & 0xffff) | ((unsigned)u.w << 16));
            a2 = __vadd2(a2, (unsigned)(v.x & 0xffff) | ((unsigned)v.y << 16));
            a3 = __vadd2(a3, (unsigned)(v.z & 0xffff) | ((unsigned)v.w << 16));
        }
        // input_bias
        {
            const int4 bA = ((const int4*)bias)[lane * 2 + 0];
            const int4 bB = ((const int4*)bias)[lane * 2 + 1];
            a0 = __vadd2(a0, (unsigned)(bA.x & 0xffff) | ((unsigned)bA.y << 16));
            a1 = __vadd2(a1, (unsigned)(bA.z & 0xffff) | ((unsigned)bA.w << 16));
            a2 = __vadd2(a2, (unsigned)(bB.x & 0xffff) | ((unsigned)bB.y << 16));
            a3 = __vadd2(a3, (unsigned)(bB.z & 0xffff) | ((unsigned)bB.w << 16));
        }

        // clip int16 -> [0,127], pack 8 int8 into 2 words
        unsigned accs[4] = {a0, a1, a2, a3};
        int c8[8];
        #pragma unroll
        for (int kk = 0; kk < 4; kk++) {
            int lo = (int)(short)(accs[kk] & 0xffffu);
            int hi = (int)(short)(accs[kk] >> 16);
            c8[2 * kk + 0] = min(max(lo, 0), 127);
            c8[2 * kk + 1] = min(max(hi, 0), 127);
        }
        s_x[warp][lane * 2 + 0] = (unsigned)c8[0] | ((unsigned)c8[1] << 8) |
                                  ((unsigned)c8[2] << 16) | ((unsigned)c8[3] << 24);
        s_x[warp][lane * 2 + 1] = (unsigned)c8[4] | ((unsigned)c8[5] << 8) |
                                  ((unsigned)c8[6] << 16) | ((unsigned)c8[7] << 24);
        __syncwarp();

        // FC1: lane = output unit; x512 = [x, x]; 4 independent dp4a chains
        int v1a = b1[lane], v1b = 0, v1c = 0, v1d = 0;
        #pragma unroll 8
        for (int j = 0; j < 64; j += 2) {
            const int x0 = (int)s_x[warp][j];
            const int x1 = (int)s_x[warp][j + 1];
            v1a = __dp4a(x0, (int)s_w1[j * 32 + lane],        v1a);
            v1b = __dp4a(x0, (int)s_w1[(64 + j) * 32 + lane], v1b);
            v1c = __dp4a(x1, (int)s_w1[(j + 1) * 32 + lane],  v1c);
            v1d = __dp4a(x1, (int)s_w1[(65 + j) * 32 + lane], v1d);
        }
        int v1 = (v1a + v1b) + (v1c + v1d);
        v1 >>= 6;
        v1 = min(max(v1, 0), 127);
        s_x1[warp][lane] = v1;
        __syncwarp();

        // FC2 (conflict-free transposed SMEM weights), 2 chains
        int v2a = b2[lane], v2b = 0;
        #pragma unroll 8
        for (int o = 0; o < 32; o += 2) {
            v2a += s_x1[warp][o]     * s_w2[o * 32 + lane];
            v2b += s_x1[warp][o + 1] * s_w2[(o + 1) * 32 + lane];
        }
        int v2 = v2a + v2b;
        v2 >>= 6;
        v2 = min(max(v2, 0), 127);

        contrib = v2 * ow[lane];
        #pragma unroll
        for (int sh = 16; sh; sh >>= 1)
            contrib += __shfl_xor_sync(0xffffffffu, contrib, sh);
    }

    if (lane == 0) s_wsum[warp] = contrib;
    __syncthreads();
    if (threadIdx.x == 0) {
        int t = 0;
        #pragma unroll
        for (int w = 0; w < 8; w++) t += s_wsum[w];
        atomicAdd(&g_total, t);
        __threadfence();
        if (atomicAdd(&g_done, 1) == nblocks - 1) {
            const int tot = atomicAdd(&g_total, 0);
            out[0] = (float)((tot + ob[0]) >> 4);
        }
    }
}

extern "C" void kernel_launch(void* const* d_in, const int* in_sizes, int n_in,
                              void* d_out, int out_size) {
    const int B = in_sizes[0] / 640;
    const int sblocks = (B + 7) / 8;

    hx_phaseA<<<dim3(64, NQ), 256>>>(
        (const int*)d_in[2], (const int*)d_in[0], (const int*)d_in[1], B);
    hx_phaseB<<<sblocks, 256>>>(
        (const int*)d_in[2],
        (const int*)d_in[1],
        (const int*)d_in[3],
        (const int*)d_in[4],
        (const int*)d_in[5],
        (const int*)d_in[6],
        (const int*)d_in[7],
        (const int*)d_in[8],
        (const int*)d_in[9],
        (float*)d_out,
        B, sblocks);
}